// round 14
// baseline (speedup 1.0000x reference)
#include <cuda_runtime.h>
#include <cuda_bf16.h>
#include <cstdint>

// Problem constants (fixed shapes)
#define ND 20000
#define NP 40000
#define EMAX 300000
#define HIDW 256
#define OUTC 64
#define NEG 0.2f

// ---------------- static device scratch (allocation-free rule) ----------------
__device__ float g_xd[2][ND * HIDW];
__device__ float g_xp[2][NP * HIDW];
__device__ float g_h[3][NP * HIDW];
__device__ float g_alpha[3 * EMAX * 4];
__device__ float g_als[3 * NP * 4];
__device__ float g_ald[NP * 4];
__device__ float g_V[9 * 1024];
__device__ int   g_rowptr[3 * (NP + 1)];
__device__ int   g_srcp[3 * EMAX];
__device__ int   g_cnt[3 * NP];
#define WTOT 540672
__device__ __nv_bfloat16 g_whi[WTOT];
__device__ __nv_bfloat16 g_wlo[WTOT];
// bf16-split activations (A operands for GEMMs)
#define XIN_TOT (ND * 128 + NP * HIDW)
__device__ __nv_bfloat16 g_xin_h[XIN_TOT];
__device__ __nv_bfloat16 g_xin_l[XIN_TOT];
__device__ __nv_bfloat16 g_xdbf_h[ND * HIDW];
__device__ __nv_bfloat16 g_xdbf_l[ND * HIDW];
__device__ __nv_bfloat16 g_xpbf_h[NP * HIDW];
__device__ __nv_bfloat16 g_xpbf_l[NP * HIDW];

// ======================= helpers =======================
__device__ __forceinline__ uint32_t smem_u32(const void* p) {
    uint32_t a;
    asm("{ .reg .u64 t; cvta.to.shared.u64 t, %1; cvt.u32.u64 %0, t; }" : "=r"(a) : "l"(p));
    return a;
}
__device__ __forceinline__ void cp_async8(uint32_t dst, const void* src) {
    asm volatile("cp.async.ca.shared.global [%0], [%1], 8;" :: "r"(dst), "l"(src));
}
#define CP_COMMIT() asm volatile("cp.async.commit_group;" ::: "memory")
#define CP_WAIT0()  asm volatile("cp.async.wait_group 0;" ::: "memory")

__device__ __forceinline__ void mma16816(float* c, const uint32_t* a, const uint32_t* b) {
    asm volatile(
        "mma.sync.aligned.m16n8k16.row.col.f32.bf16.bf16.f32 "
        "{%0,%1,%2,%3}, {%4,%5,%6,%7}, {%8,%9}, {%0,%1,%2,%3};"
        : "+f"(c[0]), "+f"(c[1]), "+f"(c[2]), "+f"(c[3])
        : "r"(a[0]), "r"(a[1]), "r"(a[2]), "r"(a[3]), "r"(b[0]), "r"(b[1]));
}
__device__ __forceinline__ void ldsm4(uint32_t* r, uint32_t addr) {
    asm volatile("ldmatrix.sync.aligned.m8n8.x4.shared.b16 {%0,%1,%2,%3}, [%4];"
                 : "=r"(r[0]), "=r"(r[1]), "=r"(r[2]), "=r"(r[3]) : "r"(addr));
}

__device__ __forceinline__ uint32_t pack_bf2(float x, float y) {
    __nv_bfloat162 t = __floats2bfloat162_rn(x, y);
    return *reinterpret_cast<uint32_t*>(&t);
}
__device__ __forceinline__ float eluf(float v) { return v > 0.f ? v : expm1f(v); }
// split v0,v1 -> hi uint32 + lo uint32
__device__ __forceinline__ void split2u(float v0, float v1, uint32_t& hi, uint32_t& lo) {
    __nv_bfloat16 a = __float2bfloat16(v0), b = __float2bfloat16(v1);
    __nv_bfloat162 H(a, b);
    hi = *reinterpret_cast<uint32_t*>(&H);
    lo = pack_bf2(v0 - __bfloat162float(a), v1 - __bfloat162float(b));
}

// ---------------- all-weights pre-transpose + bf16 split in ONE launch ----------------
__global__ void k_splitW_all(const float* __restrict__ linW_d, const float* __restrict__ linW_p,
                             const float* __restrict__ W_hid, const float* __restrict__ W_out,
                             __nv_bfloat16* __restrict__ hi, __nv_bfloat16* __restrict__ lo) {
    int id = blockIdx.y;
    int i = blockIdx.x * 256 + threadIdx.x;
    const float* W;
    size_t off;
    int K, N;
    if (id == 0) { W = linW_d; off = 0; K = 128; N = 256; }
    else if (id == 1) { W = linW_p; off = 32768; K = 256; N = 256; }
    else if (id < 8) {
        W = W_hid + (size_t)(id - 2) * 65536; off = 98304 + (size_t)(id - 2) * 65536;
        K = 256; N = 256;
    } else {
        W = W_out + (size_t)(id - 8) * 16384; off = 491520 + (size_t)(id - 8) * 16384;
        K = 256; N = 64;
    }
    if (i >= N * K) return;
    int n = i / K, k = i % K;
    float v = W[(size_t)k * N + n];
    __nv_bfloat16 h = __float2bfloat16(v);
    hi[off + i] = h;
    lo[off + i] = __float2bfloat16(v - __bfloat162float(h));
}

// ---------------- split input features to bf16 hi/lo ----------------
__global__ void k_splitX(const float* __restrict__ xd, const float* __restrict__ xp,
                         __nv_bfloat16* __restrict__ h, __nv_bfloat16* __restrict__ l) {
    int y = blockIdx.y;
    const float* src = y ? xp : xd;
    size_t off = y ? (size_t)ND * 128 : 0;
    int n = y ? NP * HIDW : ND * 128;
    int i = blockIdx.x * 256 + threadIdx.x;
    if (i >= n) return;
    float v = src[i];
    __nv_bfloat16 hh = __float2bfloat16(v);
    h[off + i] = hh;
    l[off + i] = __float2bfloat16(v - __bfloat162float(hh));
}

// ============ batched mma.sync GEMM (cfg selected by blockIdx.z) ============
struct GemmCfg {
    const __nv_bfloat16* Ahi;
    const __nv_bfloat16* Alo;
    const __nv_bfloat16* Bhi;
    const __nv_bfloat16* Blo;
    const float* bias;
    const float* asrc;
    const float* adst;
    float* C;
    __nv_bfloat16* Chi;
    __nv_bfloat16* Clo;
    float* als;
    float* ald;
    int M;
    int K;
};
struct GemmCfg3 { GemmCfg c[3]; };

template <int BN, bool BIAS, bool RELU, int HALS>
__global__ void __launch_bounds__(256, 2) k_mma(GemmCfg3 P) {
    GemmCfg cfg = P.c[blockIdx.z];
    const int M = cfg.M, K = cfg.K;
    if ((int)blockIdx.x * 128 >= M) return;

    extern __shared__ char smem[];
    constexpr int WN = BN / 2;
    constexpr int NTILES = WN / 8;
    constexpr int ABUF = 128 * 40 * 2;
    constexpr int BBUF = BN * 40 * 2;
    constexpr int S_A = 2048;
    constexpr int S_B = S_A + 4 * ABUF;
    float* sBias = (float*)(smem);
    float* sAsrc = (float*)(smem + 512);
    float* sAdst = (float*)(smem + 1024);
    __shared__ float sr1[128];
    __shared__ float sr2[128];

    const bool dual = (HALS != 0) && (cfg.adst != nullptr);

    int tid = threadIdx.x;
    int wid = tid >> 5, lane = tid & 31;
    int g = lane >> 2, tg = lane & 3;
    int warp_m = wid & 3, warp_n = wid >> 2;
    int bm = blockIdx.x * 128, bn = blockIdx.y * BN;

    if (BIAS)
        for (int i = tid; i < BN; i += 256) sBias[i] = cfg.bias[bn + i];
    if (HALS) {
        for (int i = tid; i < BN; i += 256) sAsrc[i] = cfg.asrc[bn + i];
        if (dual)
            for (int i = tid; i < BN; i += 256) sAdst[i] = cfg.adst[bn + i];
    }

    constexpr int CHB = BN * 8 / 256;  // B 8B-chunks per thread per half
    // A tile = 128x32 bf16 -> 1024 chunks -> 4 per thread per half

    float acc[2][NTILES][4];
#pragma unroll
    for (int mi = 0; mi < 2; mi++)
#pragma unroll
        for (int nt = 0; nt < NTILES; nt++)
#pragma unroll
            for (int q = 0; q < 4; q++) acc[mi][nt][q] = 0.f;

    uint32_t sbase = smem_u32(smem);
    const __nv_bfloat16* Athi = cfg.Ahi;
    const __nv_bfloat16* Atlo = cfg.Alo;
    const __nv_bfloat16* Bthi = cfg.Bhi;
    const __nv_bfloat16* Btlo = cfg.Blo;

    // ---- ldmatrix per-lane address offsets (bytes, relative to tile base) ----
    uint32_t aoff = (uint32_t)((warp_m * 32 + (lane & 15)) * 40 + ((lane >> 4) << 3)) * 2;
    uint32_t boff[NTILES / 2];
#pragma unroll
    for (int tp = 0; tp < NTILES / 2; tp++)
        boff[tp] = (uint32_t)((warp_n * WN + (tp * 2 + ((lane >> 4) & 1)) * 8 + (lane & 7)) * 40 +
                              (((lane >> 3) & 1) << 3)) * 2;

    auto loadA = [&](int k0, int buf) {
        uint32_t dh = sbase + S_A + buf * 2 * ABUF;
        uint32_t dl = dh + ABUF;
#pragma unroll
        for (int i = 0; i < 4; i++) {
            int c = tid + i * 256;
            int row = c >> 3, kc = c & 7;
            int gr = bm + row;
            if (gr >= M) gr = M - 1;  // clamp; garbage rows only feed guarded outputs
            size_t go = (size_t)gr * K + k0 + kc * 4;
            uint32_t so = row * 80 + kc * 8;
            cp_async8(dh + so, Athi + go);
            cp_async8(dl + so, Atlo + go);
        }
    };
    auto loadB = [&](int k0, int buf) {
        uint32_t dh = sbase + S_B + buf * 2 * BBUF;
        uint32_t dl = dh + BBUF;
#pragma unroll
        for (int i = 0; i < CHB; i++) {
            int c = tid + i * 256;
            int row = c >> 3, kc = c & 7;
            size_t go = (size_t)(bn + row) * K + k0 + kc * 4;
            uint32_t so = row * 80 + kc * 8;
            cp_async8(dh + so, Bthi + go);
            cp_async8(dl + so, Btlo + go);
        }
    };
    auto compute = [&](int buf) {
        uint32_t Ah = sbase + S_A + buf * 2 * ABUF;
        uint32_t Al = Ah + ABUF;
        uint32_t Bh = sbase + S_B + buf * 2 * BBUF;
        uint32_t Bl = Bh + BBUF;
#pragma unroll
        for (int kk = 0; kk < 32; kk += 16) {
            uint32_t ah[2][4], al[2][4];
#pragma unroll
            for (int mi = 0; mi < 2; mi++) {
                uint32_t o = aoff + mi * (16 * 80) + kk * 2;
                ldsm4(ah[mi], Ah + o);
                ldsm4(al[mi], Al + o);
            }
#pragma unroll
            for (int tp = 0; tp < NTILES / 2; tp++) {
                uint32_t o = boff[tp] + kk * 2;
                uint32_t bh4[4], bl4[4];
                ldsm4(bh4, Bh + o);
                ldsm4(bl4, Bl + o);
#pragma unroll
                for (int sub = 0; sub < 2; sub++) {
                    int nt = tp * 2 + sub;
                    const uint32_t* bh = bh4 + sub * 2;
                    const uint32_t* bl = bl4 + sub * 2;
#pragma unroll
                    for (int mi = 0; mi < 2; mi++) {
                        mma16816(acc[mi][nt], ah[mi], bh);
                        mma16816(acc[mi][nt], ah[mi], bl);
                        mma16816(acc[mi][nt], al[mi], bh);
                    }
                }
            }
        }
    };

    int nstages = K / 32;
    loadA(0, 0);
    loadB(0, 0);
    CP_COMMIT();
    CP_WAIT0();
    __syncthreads();
    for (int s = 0; s < nstages; s++) {
        int cur = s & 1, nxt = cur ^ 1;
        bool more = (s + 1) < nstages;
        if (more) {
            loadA((s + 1) * 32, nxt);
            loadB((s + 1) * 32, nxt);
            CP_COMMIT();
        }
        compute(cur);
        CP_WAIT0();
        __syncthreads();
    }

    // ---- epilogue ----
    const int NT = (BN == 128) ? 256 : 64;
    float sals[2][2], sald[2][2];
    sals[0][0] = sals[0][1] = sals[1][0] = sals[1][1] = 0.f;
    sald[0][0] = sald[0][1] = sald[1][0] = sald[1][1] = 0.f;
#pragma unroll
    for (int mi = 0; mi < 2; mi++) {
        int r0 = bm + warp_m * 32 + mi * 16 + g;
        int r1 = r0 + 8;
#pragma unroll
        for (int nt = 0; nt < NTILES; nt++) {
            int nloc = warp_n * WN + nt * 8 + tg * 2;
            int n0 = bn + nloc;
            float* cc = acc[mi][nt];
            float v00 = cc[0], v01 = cc[1], v10 = cc[2], v11 = cc[3];
            if (BIAS) {
                v00 += sBias[nloc]; v01 += sBias[nloc + 1];
                v10 += sBias[nloc]; v11 += sBias[nloc + 1];
            }
            if (RELU) {
                v00 = fmaxf(v00, 0.f); v01 = fmaxf(v01, 0.f);
                v10 = fmaxf(v10, 0.f); v11 = fmaxf(v11, 0.f);
            }
            if (r0 < M) {
                *(float2*)(cfg.C + (size_t)r0 * NT + n0) = make_float2(v00, v01);
                if (cfg.Chi) {
                    uint32_t hi, lo;
                    split2u(v00, v01, hi, lo);
                    *(uint32_t*)(cfg.Chi + (size_t)r0 * NT + n0) = hi;
                    *(uint32_t*)(cfg.Clo + (size_t)r0 * NT + n0) = lo;
                }
            }
            if (r1 < M) {
                *(float2*)(cfg.C + (size_t)r1 * NT + n0) = make_float2(v10, v11);
                if (cfg.Chi) {
                    uint32_t hi, lo;
                    split2u(v10, v11, hi, lo);
                    *(uint32_t*)(cfg.Chi + (size_t)r1 * NT + n0) = hi;
                    *(uint32_t*)(cfg.Clo + (size_t)r1 * NT + n0) = lo;
                }
            }
            if (HALS) {
                float a0 = sAsrc[nloc], a1 = sAsrc[nloc + 1];
                sals[mi][0] += v00 * a0 + v01 * a1;
                sals[mi][1] += v10 * a0 + v11 * a1;
                if (dual) {
                    float d0 = sAdst[nloc], d1 = sAdst[nloc + 1];
                    sald[mi][0] += v00 * d0 + v01 * d1;
                    sald[mi][1] += v10 * d0 + v11 * d1;
                }
            }
        }
    }
    if (HALS) {
        if (HALS == 1) {
            for (int i = tid; i < 128; i += 256) { sr1[i] = 0.f; sr2[i] = 0.f; }
            __syncthreads();
        }
#pragma unroll
        for (int mi = 0; mi < 2; mi++)
#pragma unroll
            for (int hf = 0; hf < 2; hf++) {
                float s = sals[mi][hf];
                s += __shfl_xor_sync(0xffffffffu, s, 1);
                s += __shfl_xor_sync(0xffffffffu, s, 2);
                float s2 = sald[mi][hf];
                s2 += __shfl_xor_sync(0xffffffffu, s2, 1);
                s2 += __shfl_xor_sync(0xffffffffu, s2, 2);
                if (tg == 0) {
                    int rloc = warp_m * 32 + mi * 16 + g + hf * 8;
                    int r = bm + rloc;
                    if (HALS == 4) {
                        if (r < M) {
                            int h = blockIdx.y * 2 + warp_n;
                            cfg.als[(size_t)r * 4 + h] = s;
                            if (dual) cfg.ald[(size_t)r * 4 + h] = s2;
                        }
                    } else {
                        atomicAdd(&sr1[rloc], s);
                        if (dual) atomicAdd(&sr2[rloc], s2);
                    }
                }
            }
        if (HALS == 1) {
            __syncthreads();
            for (int i = tid; i < 128; i += 256) {
                int r = bm + i;
                if (r < M) {
                    cfg.als[r] = sr1[i];
                    if (dual) cfg.ald[r] = sr2[i];
                }
            }
        }
    }
}

// ---------------- CSR build (batched over 3 edge types) ----------------
__global__ void k_zero(int* __restrict__ p, int n) {
    int i = blockIdx.x * blockDim.x + threadIdx.x;
    if (i < n) p[i] = 0;
}
__global__ void k_count3(const int* __restrict__ d0, const int* __restrict__ d1,
                         const int* __restrict__ d2, int E0, int E1, int E2,
                         int* __restrict__ cnt) {
    int t = blockIdx.y;
    const int* dst = (t == 0) ? d0 : (t == 1) ? d1 : d2;
    int E = (t == 0) ? E0 : (t == 1) ? E1 : E2;
    int i = blockIdx.x * 256 + threadIdx.x;
    if (i < E) atomicAdd(&cnt[t * NP + dst[i]], 1);
}
__global__ void __launch_bounds__(1024) k_scan3(int* __restrict__ cnt,
                                                int* __restrict__ rp, int n0, int n1, int n2) {
    int t = blockIdx.x;
    int n = (t == 0) ? n0 : (t == 1) ? n1 : n2;
    int* c = cnt + t * NP;
    int* rowptr = rp + t * (NP + 1);
    __shared__ int wsum[32];
    __shared__ int carry_s;
    int tid = threadIdx.x, lane = tid & 31, wid = tid >> 5;
    if (tid == 0) { carry_s = 0; rowptr[0] = 0; }
    __syncthreads();
    for (int base = 0; base < n; base += 4096) {
        int c0 = carry_s;
        int i0 = base + tid * 4;
        int v[4];
#pragma unroll
        for (int k = 0; k < 4; k++) {
            v[k] = (i0 + k < n) ? c[i0 + k] : 0;
            if (i0 + k < n) c[i0 + k] = 0;
        }
        int incl[4];
        incl[0] = v[0];
        incl[1] = incl[0] + v[1];
        incl[2] = incl[1] + v[2];
        incl[3] = incl[2] + v[3];
        int tot = incl[3];
        int x = tot;
#pragma unroll
        for (int o = 1; o < 32; o <<= 1) {
            int y = __shfl_up_sync(0xffffffffu, x, o);
            if (lane >= o) x += y;
        }
        if (lane == 31) wsum[wid] = x;
        __syncthreads();
        if (wid == 0) {
            int s = wsum[lane];
#pragma unroll
            for (int o = 1; o < 32; o <<= 1) {
                int y = __shfl_up_sync(0xffffffffu, s, o);
                if (lane >= o) s += y;
            }
            wsum[lane] = s;
        }
        __syncthreads();
        int excl = (x - tot) + (wid ? wsum[wid - 1] : 0) + c0;
#pragma unroll
        for (int k = 0; k < 4; k++) {
            int i = i0 + k;
            if (i < n) rowptr[i + 1] = excl + incl[k];
        }
        __syncthreads();
        if (tid == 0) carry_s = c0 + wsum[31];
        __syncthreads();
    }
}
__global__ void k_scatter3(const int* __restrict__ s0p, const int* __restrict__ s1p,
                           const int* __restrict__ s2p, const int* __restrict__ d0,
                           const int* __restrict__ d1, const int* __restrict__ d2,
                           int E0, int E1, int E2, const int* __restrict__ rp,
                           int* __restrict__ off, int* __restrict__ srcp) {
    int t = blockIdx.y;
    const int* src = (t == 0) ? s0p : (t == 1) ? s1p : s2p;
    const int* dst = (t == 0) ? d0 : (t == 1) ? d1 : d2;
    int E = (t == 0) ? E0 : (t == 1) ? E1 : E2;
    int i = blockIdx.x * 256 + threadIdx.x;
    if (i < E) {
        int d = dst[i];
        int p = rp[t * (NP + 1) + d] + atomicAdd(&off[t * NP + d], 1);
        srcp[t * EMAX + p] = src[i];
    }
}

// ---------------- all 9 Vd vectors in one launch ----------------
__global__ void k_makeV_all(const float* __restrict__ W_hid, const float* __restrict__ ad_hid,
                            const float* __restrict__ W_out, const float* __restrict__ ad_out,
                            float* __restrict__ V) {
    int b = blockIdx.x;
    int k = threadIdx.x;
    if (b < 6) {
        const float* W = W_hid + (size_t)b * 65536;
        const float* a = ad_hid + (size_t)b * 256;
        for (int h = 0; h < 4; h++) {
            float s = 0.f;
            for (int c = 0; c < 64; c++) s = fmaf(W[k * 256 + h * 64 + c], a[h * 64 + c], s);
            V[b * 1024 + k * 4 + h] = s;
        }
    } else {
        const float* W = W_out + (size_t)(b - 6) * 16384;
        const float* a = ad_out + (size_t)(b - 6) * 64;
        float s = 0.f;
        for (int c = 0; c < 64; c++) s = fmaf(W[k * 64 + c], a[c], s);
        V[b * 1024 + k] = s;
    }
}

// ---------------- per-segment softmax+gather accumulate, H=4 ----------------
__device__ __forceinline__ void edge4(const int* __restrict__ rowptr,
                                      const int* __restrict__ srcp,
                                      const float* __restrict__ als, const float* ad,
                                      const float* __restrict__ hsrc,
                                      float* __restrict__ alpha, int w, int lane, int c0,
                                      int c1, int hsel, float4& a0, float4& a1) {
    int s0 = rowptr[w], s1 = rowptr[w + 1];
    int deg = s1 - s0;
    if (deg <= 0) return;
    const float NINF = __int_as_float(0xff800000u);
    if (deg <= 32) {
        int sreg = (lane < deg) ? srcp[s0 + lane] : 0;
        float ex[4];
#pragma unroll
        for (int h = 0; h < 4; h++) {
            float e = NINF;
            if (lane < deg) {
                e = als[(size_t)sreg * 4 + h] + ad[h];
                e = e > 0.f ? e : NEG * e;
            }
            ex[h] = e;
        }
        float inv[4];
#pragma unroll
        for (int h = 0; h < 4; h++) {
            float m = ex[h];
#pragma unroll
            for (int o = 16; o; o >>= 1) m = fmaxf(m, __shfl_xor_sync(0xffffffffu, m, o));
            float v = (lane < deg) ? __expf(ex[h] - m) : 0.f;
            ex[h] = v;
#pragma unroll
            for (int o = 16; o; o >>= 1) v += __shfl_xor_sync(0xffffffffu, v, o);
            inv[h] = 1.f / (v + 1e-16f);
        }
        float inv0 = hsel ? inv[1] : inv[0];
        float inv1 = hsel ? inv[3] : inv[2];
        for (int i = 0; i < deg; i++) {
            int s = __shfl_sync(0xffffffffu, sreg, i);
            float e0 = __shfl_sync(0xffffffffu, ex[0], i);
            float e1 = __shfl_sync(0xffffffffu, ex[1], i);
            float e2 = __shfl_sync(0xffffffffu, ex[2], i);
            float e3 = __shfl_sync(0xffffffffu, ex[3], i);
            float w0 = (hsel ? e1 : e0) * inv0;
            float w1 = (hsel ? e3 : e2) * inv1;
            const float4* hr = (const float4*)(hsrc + (size_t)s * 256);
            float4 v0 = hr[c0], v1 = hr[c1];
            a0.x = fmaf(v0.x, w0, a0.x); a0.y = fmaf(v0.y, w0, a0.y);
            a0.z = fmaf(v0.z, w0, a0.z); a0.w = fmaf(v0.w, w0, a0.w);
            a1.x = fmaf(v1.x, w1, a1.x); a1.y = fmaf(v1.y, w1, a1.y);
            a1.z = fmaf(v1.z, w1, a1.z); a1.w = fmaf(v1.w, w1, a1.w);
        }
    } else {
        float mx[4], sm[4], inv[4];
#pragma unroll
        for (int h = 0; h < 4; h++) { mx[h] = NINF; sm[h] = 0.f; }
        for (int j = s0 + lane; j < s1; j += 32) {
            int s = srcp[j];
#pragma unroll
            for (int h = 0; h < 4; h++) {
                float e = als[(size_t)s * 4 + h] + ad[h];
                e = e > 0.f ? e : NEG * e;
                alpha[(size_t)j * 4 + h] = e;
                mx[h] = fmaxf(mx[h], e);
            }
        }
#pragma unroll
        for (int h = 0; h < 4; h++)
#pragma unroll
            for (int o = 16; o; o >>= 1)
                mx[h] = fmaxf(mx[h], __shfl_xor_sync(0xffffffffu, mx[h], o));
        for (int j = s0 + lane; j < s1; j += 32) {
#pragma unroll
            for (int h = 0; h < 4; h++) {
                float e2 = __expf(alpha[(size_t)j * 4 + h] - mx[h]);
                alpha[(size_t)j * 4 + h] = e2;
                sm[h] += e2;
            }
        }
#pragma unroll
        for (int h = 0; h < 4; h++) {
#pragma unroll
            for (int o = 16; o; o >>= 1) sm[h] += __shfl_xor_sync(0xffffffffu, sm[h], o);
            inv[h] = 1.f / (sm[h] + 1e-16f);
        }
        float inv0 = inv[hsel], inv1 = inv[hsel + 2];
        for (int j = s0; j < s1; j++) {
            int s = srcp[j];
            float4 al = *(const float4*)(alpha + (size_t)j * 4);
            const float4* hr = (const float4*)(hsrc + (size_t)s * 256);
            float4 v0 = hr[c0], v1 = hr[c1];
            float w0 = (hsel ? al.y : al.x) * inv0;
            float w1 = (hsel ? al.w : al.z) * inv1;
            a0.x = fmaf(v0.x, w0, a0.x); a0.y = fmaf(v0.y, w0, a0.y);
            a0.z = fmaf(v0.z, w0, a0.z); a0.w = fmaf(v0.w, w0, a0.w);
            a1.x = fmaf(v1.x, w1, a1.x); a1.y = fmaf(v1.y, w1, a1.y);
            a1.z = fmaf(v1.z, w1, a1.z); a1.w = fmaf(v1.w, w1, a1.w);
        }
    }
}

// ---------------- mega aggregation: one launch per hidden layer ----------------
// also writes bf16 hi/lo splits of outputs (A operand of the next GEMM)
__global__ void __launch_bounds__(256) k_lagg4(
    const int* __restrict__ rp0, const int* __restrict__ sp0, const int* __restrict__ rp1,
    const int* __restrict__ sp1, const int* __restrict__ rp2, const int* __restrict__ sp2,
    const float* __restrict__ h0, const float* __restrict__ h1, const float* __restrict__ h2,
    const float* __restrict__ als0, const float* __restrict__ als1,
    const float* __restrict__ als2, const float* __restrict__ ald2,
    const float* __restrict__ V0, const float* __restrict__ V1,
    const float* __restrict__ xp_in, const float* __restrict__ xd_in,
    const float* __restrict__ b0, const float* __restrict__ b1, const float* __restrict__ b2,
    float* __restrict__ alpha0, float* __restrict__ alpha1, float* __restrict__ alpha2,
    float* __restrict__ xp_out, float* __restrict__ xd_out,
    __nv_bfloat16* __restrict__ xph, __nv_bfloat16* __restrict__ xpl,
    __nv_bfloat16* __restrict__ xdh, __nv_bfloat16* __restrict__ xdl, int act) {
    __shared__ float Vs0[1024];
    __shared__ float Vs1[1024];
    for (int i = threadIdx.x; i < 1024; i += 256) {
        Vs0[i] = V0[i];
        Vs1[i] = V1[i];
    }
    __syncthreads();
    int n = (blockIdx.x * 256 + threadIdx.x) >> 5;
    int lane = threadIdx.x & 31;
    if (n >= NP + ND) return;
    int c0 = lane, c1 = lane + 32, hsel = lane >> 4;
    float4 a0 = make_float4(0.f, 0.f, 0.f, 0.f), a1 = a0;
    float4 o0, o1;
    float4* orow;
    __nv_bfloat16 *oh, *ol;
    size_t obase;
    if (n < NP) {
        int w = n;
        const float* xr = xp_in + (size_t)w * 256;
        float p[4] = {0.f, 0.f, 0.f, 0.f};
#pragma unroll
        for (int tt = 0; tt < 8; tt++) {
            int k = lane + tt * 32;
            float x = xr[k];
#pragma unroll
            for (int h = 0; h < 4; h++) p[h] = fmaf(x, Vs0[k * 4 + h], p[h]);
        }
        float ad0[4];
#pragma unroll
        for (int h = 0; h < 4; h++) {
#pragma unroll
            for (int o = 16; o; o >>= 1) p[h] += __shfl_xor_sync(0xffffffffu, p[h], o);
            ad0[h] = p[h];
        }
        float ad2[4];
#pragma unroll
        for (int h = 0; h < 4; h++) ad2[h] = ald2[(size_t)w * 4 + h];
        edge4(rp0, sp0, als0, ad0, h0, alpha0, w, lane, c0, c1, hsel, a0, a1);
        edge4(rp2, sp2, als2, ad2, h2, alpha2, w, lane, c0, c1, hsel, a0, a1);
        const float4* B0 = (const float4*)b0;
        const float4* B2 = (const float4*)b2;
        float4 bb0 = B0[c0], bb1 = B0[c1];
        float4 t0 = B2[c0], t1 = B2[c1];
        bb0.x += t0.x; bb0.y += t0.y; bb0.z += t0.z; bb0.w += t0.w;
        bb1.x += t1.x; bb1.y += t1.y; bb1.z += t1.z; bb1.w += t1.w;
        o0 = make_float4(a0.x + bb0.x, a0.y + bb0.y, a0.z + bb0.z, a0.w + bb0.w);
        o1 = make_float4(a1.x + bb1.x, a1.y + bb1.y, a1.z + bb1.z, a1.w + bb1.w);
        orow = (float4*)(xp_out + (size_t)w * 256);
        oh = xph; ol = xpl; obase = (size_t)w * 256;
    } else {
        int w = n - NP;
        const float* xr = xd_in + (size_t)w * 256;
        float p[4] = {0.f, 0.f, 0.f, 0.f};
#pragma unroll
        for (int tt = 0; tt < 8; tt++) {
            int k = lane + tt * 32;
            float x = xr[k];
#pragma unroll
            for (int h = 0; h < 4; h++) p[h] = fmaf(x, Vs1[k * 4 + h], p[h]);
        }
        float ad1[4];
#pragma unroll
        for (int h = 0; h < 4; h++) {
#pragma unroll
            for (int o = 16; o; o >>= 1) p[h] += __shfl_xor_sync(0xffffffffu, p[h], o);
            ad1[h] = p[h];
        }
        edge4(rp1, sp1, als1, ad1, h1, alpha1, w, lane, c0, c1, hsel, a0, a1);
        const float4* B1 = (const float4*)b1;
        float4 bb0 = B1[c0], bb1 = B1[c1];
        o0 = make_float4(a0.x + bb0.x, a0.y + bb0.y, a0.z + bb0.z, a0.w + bb0.w);
        o1 = make_float4(a1.x + bb1.x, a1.y + bb1.y, a1.z + bb1.z, a1.w + bb1.w);
        orow = (float4*)(xd_out + (size_t)w * 256);
        oh = xdh; ol = xdl; obase = (size_t)w * 256;
    }
    if (act) {
        o0.x = eluf(o0.x); o0.y = eluf(o0.y); o0.z = eluf(o0.z); o0.w = eluf(o0.w);
        o1.x = eluf(o1.x); o1.y = eluf(o1.y); o1.z = eluf(o1.z); o1.w = eluf(o1.w);
    }
    orow[c0] = o0;
    orow[c1] = o1;
    // bf16 hi/lo split of outputs
    {
        uint32_t h1w, l1w, h2w, l2w;
        split2u(o0.x, o0.y, h1w, l1w);
        split2u(o0.z, o0.w, h2w, l2w);
        *(uint2*)(oh + obase + 4 * lane) = make_uint2(h1w, h2w);
        *(uint2*)(ol + obase + 4 * lane) = make_uint2(l1w, l2w);
        split2u(o1.x, o1.y, h1w, l1w);
        split2u(o1.z, o1.w, h2w, l2w);
        *(uint2*)(oh + obase + 128 + 4 * lane) = make_uint2(h1w, h2w);
        *(uint2*)(ol + obase + 128 + 4 * lane) = make_uint2(l1w, l2w);
    }
}

// ---------------- per-segment softmax+gather, H=1, 64 cols ----------------
__device__ __forceinline__ void edge1(const int* __restrict__ rowptr,
                                      const int* __restrict__ srcp,
                                      const float* __restrict__ als, float ad,
                                      const float* __restrict__ hsrc,
                                      float* __restrict__ alpha, int w, int lane, float& a0,
                                      float& a1) {
    int s0 = rowptr[w], s1 = rowptr[w + 1];
    int deg = s1 - s0;
    if (deg <= 0) return;
    const float NINF = __int_as_float(0xff800000u);
    if (deg <= 32) {
        int sreg = (lane < deg) ? srcp[s0 + lane] : 0;
        float e = NINF;
        if (lane < deg) {
            e = als[sreg] + ad;
            e = e > 0.f ? e : NEG * e;
        }
        float m = e;
#pragma unroll
        for (int o = 16; o; o >>= 1) m = fmaxf(m, __shfl_xor_sync(0xffffffffu, m, o));
        float ex = (lane < deg) ? __expf(e - m) : 0.f;
        float sm = ex;
#pragma unroll
        for (int o = 16; o; o >>= 1) sm += __shfl_xor_sync(0xffffffffu, sm, o);
        float inv = 1.f / (sm + 1e-16f);
        for (int i = 0; i < deg; i++) {
            int s = __shfl_sync(0xffffffffu, sreg, i);
            float al = __shfl_sync(0xffffffffu, ex, i) * inv;
            const float* hr = hsrc + (size_t)s * 64;
            a0 = fmaf(hr[lane], al, a0);
            a1 = fmaf(hr[lane + 32], al, a1);
        }
    } else {
        float mx = NINF, sm = 0.f;
        for (int j = s0 + lane; j < s1; j += 32) {
            int s = srcp[j];
            float e = als[s] + ad;
            e = e > 0.f ? e : NEG * e;
            alpha[j] = e;
            mx = fmaxf(mx, e);
        }
#pragma unroll
        for (int o = 16; o; o >>= 1) mx = fmaxf(mx, __shfl_xor_sync(0xffffffffu, mx, o));
        for (int j = s0 + lane; j < s1; j += 32) {
            float ex = __expf(alpha[j] - mx);
            alpha[j] = ex;
            sm += ex;
        }
#pragma unroll
        for (int o = 16; o; o >>= 1) sm += __shfl_xor_sync(0xffffffffu, sm, o);
        float inv = 1.f / (sm + 1e-16f);
        for (int j = s0; j < s1; j++) {
            int s = srcp[j];
            float al = alpha[j] * inv;
            const float* hr = hsrc + (size_t)s * 64;
            a0 = fmaf(hr[lane], al, a0);
            a1 = fmaf(hr[lane + 32], al, a1);
        }
    }
}

// ---------------- mega aggregation for output layer ----------------
__global__ void __launch_bounds__(256) k_lagg1(
    const int* __restrict__ rp0, const int* __restrict__ sp0, const int* __restrict__ rp1,
    const int* __restrict__ sp1, const int* __restrict__ rp2, const int* __restrict__ sp2,
    const float* __restrict__ h0, const float* __restrict__ h1, const float* __restrict__ h2,
    const float* __restrict__ als0, const float* __restrict__ als1,
    const float* __restrict__ als2, const float* __restrict__ ald2,
    const float* __restrict__ V0, const float* __restrict__ V1,
    const float* __restrict__ xp_in, const float* __restrict__ xd_in,
    const float* __restrict__ b0, const float* __restrict__ b1, const float* __restrict__ b2,
    float* __restrict__ alpha0, float* __restrict__ alpha1, float* __restrict__ alpha2,
    float* __restrict__ op, float* __restrict__ od) {
    __shared__ float Vs0[256];
    __shared__ float Vs1[256];
    for (int i = threadIdx.x; i < 256; i += 256) {
        Vs0[i] = V0[i];
        Vs1[i] = V1[i];
    }
    __syncthreads();
    int n = (blockIdx.x * 256 + threadIdx.x) >> 5;
    int lane = threadIdx.x & 31;
    if (n >= NP + ND) return;
    float a0 = 0.f, a1 = 0.f;
    float* orow;
    float bb0, bb1;
    if (n < NP) {
        int w = n;
        const float* xr = xp_in + (size_t)w * 256;
        float p = 0.f;
#pragma unroll
        for (int tt = 0; tt < 8; tt++) {
            int k = lane + tt * 32;
            p = fmaf(xr[k], Vs0[k], p);
        }
#pragma unroll
        for (int o = 16; o; o >>= 1) p += __shfl_xor_sync(0xffffffffu, p, o);
        edge1(rp0, sp0, als0, p, h0, alpha0, w, lane, a0, a1);
        edge1(rp2, sp2, als2, ald2[w], h2, alpha2, w, lane, a0, a1);
        bb0 = b0[lane] + b2[lane];
        bb1 = b0[lane + 32] + b2[lane + 32];
        orow = op + (size_t)w * 64;
    } else {
        int w = n - NP;
        const float* xr = xd_in + (size_t)w * 256;
        float p = 0.f;
#pragma unroll
        for (int tt = 0; tt < 8; tt++) {
            int k = lane + tt * 32;
            p = fmaf(xr[k], Vs1[k], p);
        }
#pragma unroll
        for (int o = 16; o; o >>= 1) p += __shfl_xor_sync(0xffffffffu, p, o);
        edge1(rp1, sp1, als1, p, h1, alpha1, w, lane, a0, a1);
        bb0 = b1[lane];
        bb1 = b1[lane + 32];
        orow = od + (size_t)w * 64;
    }
    orow[lane] = a0 + bb0;
    orow[lane + 32] = a1 + bb1;
}

// =====================================================================
extern "C" void kernel_launch(void* const* d_in, const int* in_sizes, int n_in,
                              void* d_out, int out_size) {
    const float* x_drug = (const float*)d_in[0];
    const float* x_prot = (const float*)d_in[1];
    const int* srcA[3] = {(const int*)d_in[2], (const int*)d_in[4], (const int*)d_in[6]};
    const int* dstA[3] = {(const int*)d_in[3], (const int*)d_in[5], (const int*)d_in[7]};
    const float* linW_d = (const float*)d_in[8];
    const float* linb_d = (const float*)d_in[9];
    const float* linW_p = (const float*)d_in[10];
    const float* linb_p = (const float*)d_in[11];
    const float* W_hid = (const float*)d_in[12];
    const float* as_hid = (const float*)d_in[13];
    const float* ad_hid = (const float*)d_in[14];
    const float* b_hid = (const float*)d_in[15];
    const float* W_out = (const float*)d_in[16];
    const float* as_out = (const float*)d_in[17];
    const float* ad_out = (const float*)d_in[18];
    const float* b_out = (const float*)d_in[19];
    float* outp = (float*)d_out;

    int E[3] = {in_sizes[2], in_sizes[4], in_sizes[6]};
    int maxE = E[0] > E[1] ? E[0] : E[1];
    if (E[2] > maxE) maxE = E[2];

    float *xdb, *xpb, *hb, *alpha, *als, *ald, *V;
    int *rp, *sp, *cnt;
    __nv_bfloat16 *whi, *wlo, *xinh, *xinl, *xdh, *xdl, *xph, *xpl;
    cudaGetSymbolAddress((void**)&xdb, g_xd);
    cudaGetSymbolAddress((void**)&xpb, g_xp);
    cudaGetSymbolAddress((void**)&hb, g_h);
    cudaGetSymbolAddress((void**)&alpha, g_alpha);
    cudaGetSymbolAddress((void**)&als, g_als);
    cudaGetSymbolAddress((void**)&ald, g_ald);
    cudaGetSymbolAddress((void**)&V, g_V);
    cudaGetSymbolAddress((void**)&rp, g_rowptr);
    cudaGetSymbolAddress((void**)&sp, g_srcp);
    cudaGetSymbolAddress((void**)&cnt, g_cnt);
    cudaGetSymbolAddress((void**)&whi, g_whi);
    cudaGetSymbolAddress((void**)&wlo, g_wlo);
    cudaGetSymbolAddress((void**)&xinh, g_xin_h);
    cudaGetSymbolAddress((void**)&xinl, g_xin_l);
    cudaGetSymbolAddress((void**)&xdh, g_xdbf_h);
    cudaGetSymbolAddress((void**)&xdl, g_xdbf_l);
    cudaGetSymbolAddress((void**)&xph, g_xpbf_h);
    cudaGetSymbolAddress((void**)&xpl, g_xpbf_l);

    float* xd[2] = {xdb, xdb + (size_t)ND * HIDW};
    float* xp[2] = {xpb, xpb + (size_t)NP * HIDW};
    float* h0 = hb;
    float* h1 = hb + (size_t)NP * HIDW;
    float* h2 = hb + 2 * (size_t)NP * HIDW;
    int* rowptr[3] = {rp, rp + (NP + 1), rp + 2 * (NP + 1)};
    int* srcp[3] = {sp, sp + EMAX, sp + 2 * EMAX};
    float* als0 = als;
    float* als1 = als + (size_t)NP * 4;
    float* als2 = als + 2 * (size_t)NP * 4;
    float* alpha0 = alpha;
    float* alpha1 = alpha + (size_t)EMAX * 4;
    float* alpha2 = alpha + 2 * (size_t)EMAX * 4;

    const int SM128 = 2048 + 4 * (128 * 40 * 2) + 4 * (128 * 40 * 2);  // 83968
    const int SM64 = 2048 + 4 * (128 * 40 * 2) + 4 * (64 * 40 * 2);    // 63488
    cudaFuncSetAttribute(k_mma<128, true, true, 0>,
                         cudaFuncAttributeMaxDynamicSharedMemorySize, SM128);
    cudaFuncSetAttribute(k_mma<128, false, false, 4>,
                         cudaFuncAttributeMaxDynamicSharedMemorySize, SM128);
    cudaFuncSetAttribute(k_mma<64, false, false, 1>,
                         cudaFuncAttributeMaxDynamicSharedMemorySize, SM64);

    size_t o_lind = 0;
    size_t o_linp = 32768;
    size_t o_hid0 = 98304;
    size_t o_out0 = 491520;
    size_t o_xprot = (size_t)ND * 128;  // x_prot split offset within g_xin

    int ebx = (maxE + 255) / 256;
    int gx128 = (NP + 127) / 128;

    // L0: zero cnt
    k_zero<<<(3 * NP + 255) / 256, 256>>>(cnt, 3 * NP);
    // L1: count
    {
        dim3 gc(ebx, 3);
        k_count3<<<gc, 256>>>(dstA[0], dstA[1], dstA[2], E[0], E[1], E[2], cnt);
    }
    // L2: weight split
    {
        dim3 gw(256, 11);
        k_splitW_all<<<gw, 256>>>(linW_d, linW_p, W_hid, W_out, whi, wlo);
    }
    // L3: input feature split
    {
        dim3 gs((NP * HIDW + 255) / 256, 2);
        k_splitX<<<gs, 256>>>(x_drug, x_prot, xinh, xinl);
    }
    // L4: input projections (batched z=2) — writes fp32 + bf16 splits
    {
        GemmCfg3 P{};
        P.c[0] = {xinh, xinl, whi + o_lind, wlo + o_lind, linb_d, nullptr, nullptr,
                  xd[0], xdh, xdl, nullptr, nullptr, ND, 128};
        P.c[1] = {xinh + o_xprot, xinl + o_xprot, whi + o_linp, wlo + o_linp, linb_p,
                  nullptr, nullptr, xp[0], xph, xpl, nullptr, nullptr, NP, 256};
        P.c[2] = P.c[1];
        dim3 gg(gx128, 2, 2);
        k_mma<128, true, true, 0><<<gg, 256, SM128>>>(P);
    }
    // L5: scan (+re-zero cnt)
    k_scan3<<<3, 1024>>>(cnt, rp, NP, ND, NP);
    // L6: scatter
    {
        dim3 gs(ebx, 3);
        k_scatter3<<<gs, 256>>>(srcA[0], srcA[1], srcA[2], dstA[0], dstA[1], dstA[2], E[0],
                                E[1], E[2], rp, cnt, sp);
    }
    // L7: V vectors
    k_makeV_all<<<9, 256>>>(W_hid, ad_hid, W_out, ad_out, V);

    int cur = 0, nxt = 1;
    int naggb = (NP + ND + 7) / 8;

    // ---- hidden layers ----
    for (int l = 0; l < 2; l++) {
        int i0 = l * 3 + 0, i1 = l * 3 + 1, i2 = l * 3 + 2;
        {
            GemmCfg3 P{};
            P.c[0] = {xdh, xdl, whi + o_hid0 + (size_t)i0 * 65536,
                      wlo + o_hid0 + (size_t)i0 * 65536, nullptr,
                      as_hid + (size_t)i0 * 256, nullptr, h0, nullptr, nullptr, als0,
                      nullptr, ND, 256};
            P.c[1] = {xph, xpl, whi + o_hid0 + (size_t)i1 * 65536,
                      wlo + o_hid0 + (size_t)i1 * 65536, nullptr,
                      as_hid + (size_t)i1 * 256, nullptr, h1, nullptr, nullptr, als1,
                      nullptr, NP, 256};
            P.c[2] = {xph, xpl, whi + o_hid0 + (size_t)i2 * 65536,
                      wlo + o_hid0 + (size_t)i2 * 65536, nullptr,
                      as_hid + (size_t)i2 * 256, ad_hid + (size_t)i2 * 256, h2, nullptr,
                      nullptr, als2, ald, NP, 256};
            dim3 gg(gx128, 2, 3);
            k_mma<128, false, false, 4><<<gg, 256, SM128>>>(P);
        }
        // mega aggregation (overwrites xdh/xdl/xph/xpl AFTER the GEMM read them)
        k_lagg4<<<naggb, 256>>>(rowptr[0], srcp[0], rowptr[1], srcp[1], rowptr[2], srcp[2],
                                h0, h1, h2, als0, als1, als2, ald, V + (size_t)i0 * 1024,
                                V + (size_t)i1 * 1024, xp[cur], xd[cur],
                                b_hid + (size_t)i0 * 256, b_hid + (size_t)i1 * 256,
                                b_hid + (size_t)i2 * 256, alpha0, alpha1, alpha2, xp[nxt],
                                xd[nxt], xph, xpl, xdh, xdl, 1);
        cur = nxt;
        nxt = 1 - nxt;
    }

    // ---- output layer ----
    float* od = outp;
    float* op = outp + (size_t)ND * OUTC;
    {
        GemmCfg3 P{};
        P.c[0] = {xdh, xdl, whi + o_out0, wlo + o_out0, nullptr, as_out, nullptr,
                  h0, nullptr, nullptr, als0, nullptr, ND, 256};
        P.c[1] = {xph, xpl, whi + o_out0 + 16384, wlo + o_out0 + 16384, nullptr,
                  as_out + OUTC, nullptr, h1, nullptr, nullptr, als1, nullptr, NP, 256};
        P.c[2] = {xph, xpl, whi + o_out0 + 2 * 16384, wlo + o_out0 + 2 * 16384, nullptr,
                  as_out + 2 * OUTC, ad_out + 2 * OUTC, h2, nullptr, nullptr, als2, ald,
                  NP, 256};
        dim3 gg(gx128, 1, 3);
        k_mma<64, false, false, 1><<<gg, 256, SM64>>>(P);
    }
    k_lagg1<<<naggb, 256>>>(rowptr[0], srcp[0], rowptr[1], srcp[1], rowptr[2], srcp[2], h0,
                            h1, h2, als0, als1, als2, ald, V + 6 * 1024, V + 7 * 1024,
                            xp[cur], xd[cur], b_out + 0 * OUTC, b_out + 1 * OUTC,
                            b_out + 2 * OUTC, alpha0, alpha1, alpha2, op, od);

    (void)n_in;
    (void)out_size;
}

// round 16
// speedup vs baseline: 1.1028x; 1.1028x over previous
#include <cuda_runtime.h>
#include <cuda_bf16.h>
#include <cstdint>

// Problem constants (fixed shapes)
#define ND 20000
#define NP 40000
#define EMAX 300000
#define HIDW 256
#define OUTC 64
#define NEG 0.2f

// ---------------- static device scratch (allocation-free rule) ----------------
__device__ float g_xd[2][ND * HIDW];
__device__ float g_xp[2][NP * HIDW];
__device__ float g_h[3][NP * HIDW];
__device__ float g_alpha[3 * EMAX * 4];
__device__ float g_als[3 * NP * 4];
__device__ float g_ald[NP * 4];
__device__ float g_V[9 * 1024];
__device__ int   g_rowptr[3 * (NP + 1)];
__device__ int   g_srcp[3 * EMAX];
__device__ int   g_cnt[3 * NP];   // zero-initialized; every replay leaves it zeroed
#define WTOT 540672
__device__ __nv_bfloat16 g_whi[WTOT];
__device__ __nv_bfloat16 g_wlo[WTOT];

// ======================= helpers =======================
__device__ __forceinline__ uint32_t smem_u32(const void* p) {
    uint32_t a;
    asm("{ .reg .u64 t; cvta.to.shared.u64 t, %1; cvt.u32.u64 %0, t; }" : "=r"(a) : "l"(p));
    return a;
}
__device__ __forceinline__ void cp_async8(uint32_t dst, const void* src) {
    asm volatile("cp.async.ca.shared.global [%0], [%1], 8;" :: "r"(dst), "l"(src));
}
#define CP_COMMIT() asm volatile("cp.async.commit_group;" ::: "memory")
#define CP_WAIT0()  asm volatile("cp.async.wait_group 0;" ::: "memory")

__device__ __forceinline__ void mma16816(float* c, const uint32_t* a, const uint32_t* b) {
    asm volatile(
        "mma.sync.aligned.m16n8k16.row.col.f32.bf16.bf16.f32 "
        "{%0,%1,%2,%3}, {%4,%5,%6,%7}, {%8,%9}, {%0,%1,%2,%3};"
        : "+f"(c[0]), "+f"(c[1]), "+f"(c[2]), "+f"(c[3])
        : "r"(a[0]), "r"(a[1]), "r"(a[2]), "r"(a[3]), "r"(b[0]), "r"(b[1]));
}
__device__ __forceinline__ void ldsm4(uint32_t* r, uint32_t addr) {
    asm volatile("ldmatrix.sync.aligned.m8n8.x4.shared.b16 {%0,%1,%2,%3}, [%4];"
                 : "=r"(r[0]), "=r"(r[1]), "=r"(r[2]), "=r"(r[3]) : "r"(addr));
}

__device__ __forceinline__ uint32_t pack_bf2(float x, float y) {
    __nv_bfloat162 t = __floats2bfloat162_rn(x, y);
    return *reinterpret_cast<uint32_t*>(&t);
}
__device__ __forceinline__ float eluf(float v) { return v > 0.f ? v : expm1f(v); }

// ---------------- all-weights pre-transpose + bf16 split in ONE launch ----------------
__global__ void k_splitW_all(const float* __restrict__ linW_d, const float* __restrict__ linW_p,
                             const float* __restrict__ W_hid, const float* __restrict__ W_out,
                             __nv_bfloat16* __restrict__ hi, __nv_bfloat16* __restrict__ lo) {
    int id = blockIdx.y;
    int i = blockIdx.x * 256 + threadIdx.x;
    const float* W;
    size_t off;
    int K, N;
    if (id == 0) { W = linW_d; off = 0; K = 128; N = 256; }
    else if (id == 1) { W = linW_p; off = 32768; K = 256; N = 256; }
    else if (id < 8) {
        W = W_hid + (size_t)(id - 2) * 65536; off = 98304 + (size_t)(id - 2) * 65536;
        K = 256; N = 256;
    } else {
        W = W_out + (size_t)(id - 8) * 16384; off = 491520 + (size_t)(id - 8) * 16384;
        K = 256; N = 64;
    }
    if (i >= N * K) return;
    int n = i / K, k = i % K;
    float v = W[(size_t)k * N + n];
    __nv_bfloat16 h = __float2bfloat16(v);
    hi[off + i] = h;
    lo[off + i] = __float2bfloat16(v - __bfloat162float(h));
}

// ============ batched mma.sync GEMM (cfg selected by blockIdx.z) ============
struct GemmCfg {
    const float* A;
    const __nv_bfloat16* Bhi;
    const __nv_bfloat16* Blo;
    const float* bias;
    const float* asrc;
    const float* adst;
    float* C;
    float* als;
    float* ald;
    int M;
    int K;
};
struct GemmCfg3 { GemmCfg c[3]; };

template <int BN, bool BIAS, bool RELU, int HALS>
__global__ void __launch_bounds__(256, 2) k_mma(GemmCfg3 P) {
    GemmCfg cfg = P.c[blockIdx.z];
    const int M = cfg.M, K = cfg.K;
    if ((int)blockIdx.x * 128 >= M) return;

    extern __shared__ char smem[];
    constexpr int WN = BN / 2;
    constexpr int NTILES = WN / 8;
    constexpr int ABUF = 128 * 40 * 2;
    constexpr int BBUF = BN * 40 * 2;
    constexpr int S_A = 2048;
    constexpr int S_B = S_A + 4 * ABUF;
    float* sBias = (float*)(smem);
    float* sAsrc = (float*)(smem + 512);
    float* sAdst = (float*)(smem + 1024);
    __shared__ float sr1[128];
    __shared__ float sr2[128];

    const bool dual = (HALS != 0) && (cfg.adst != nullptr);

    int tid = threadIdx.x;
    int wid = tid >> 5, lane = tid & 31;
    int g = lane >> 2, tg = lane & 3;
    int warp_m = wid & 3, warp_n = wid >> 2;
    int bm = blockIdx.x * 128, bn = blockIdx.y * BN;

    if (BIAS)
        for (int i = tid; i < BN; i += 256) sBias[i] = cfg.bias[bn + i];
    if (HALS) {
        for (int i = tid; i < BN; i += 256) sAsrc[i] = cfg.asrc[bn + i];
        if (dual)
            for (int i = tid; i < BN; i += 256) sAdst[i] = cfg.adst[bn + i];
    }

    int arow = tid >> 1;
    int akq = (tid & 1) * 16;
    bool aval_base = (bm + arow) < M;
    constexpr int CH = BN * 8 / 256;

    float acc[2][NTILES][4];
#pragma unroll
    for (int mi = 0; mi < 2; mi++)
#pragma unroll
        for (int nt = 0; nt < NTILES; nt++)
#pragma unroll
            for (int q = 0; q < 4; q++) acc[mi][nt][q] = 0.f;

    uint32_t sbase = smem_u32(smem);
    const float* A = cfg.A;
    const __nv_bfloat16* Bthi = cfg.Bhi;
    const __nv_bfloat16* Btlo = cfg.Blo;

    // ---- ldmatrix per-lane address offsets (bytes, relative to tile base) ----
    uint32_t aoff = (uint32_t)((warp_m * 32 + (lane & 15)) * 40 + ((lane >> 4) << 3)) * 2;
    uint32_t boff[NTILES / 2];
#pragma unroll
    for (int tp = 0; tp < NTILES / 2; tp++)
        boff[tp] = (uint32_t)((warp_n * WN + (tp * 2 + ((lane >> 4) & 1)) * 8 + (lane & 7)) * 40 +
                              (((lane >> 3) & 1) << 3)) * 2;

    auto loadA = [&](int k0, float4* ar) {
        const float* src = A + (size_t)(bm + arow) * K + k0 + akq;
#pragma unroll
        for (int i = 0; i < 4; i++)
            ar[i] = aval_base ? ((const float4*)src)[i] : make_float4(0.f, 0.f, 0.f, 0.f);
    };
    auto storeA = [&](const float4* ar, int buf) {
        char* dh = smem + S_A + buf * 2 * ABUF;
        char* dl = dh + ABUF;
#pragma unroll
        for (int i = 0; i < 4; i++) {
            float4 f = ar[i];
            __nv_bfloat16 hx = __float2bfloat16(f.x), hy = __float2bfloat16(f.y);
            __nv_bfloat16 hz = __float2bfloat16(f.z), hw = __float2bfloat16(f.w);
            __nv_bfloat162 H01(hx, hy), H23(hz, hw);
            uint32_t h01 = *(uint32_t*)&H01, h23 = *(uint32_t*)&H23;
            uint32_t l01 = pack_bf2(f.x - __bfloat162float(hx), f.y - __bfloat162float(hy));
            uint32_t l23 = pack_bf2(f.z - __bfloat162float(hz), f.w - __bfloat162float(hw));
            int off = (arow * 40 + akq + i * 4) * 2;
            *(uint2*)(dh + off) = make_uint2(h01, h23);
            *(uint2*)(dl + off) = make_uint2(l01, l23);
        }
    };
    auto loadB = [&](int k0, int buf) {
        uint32_t dh = sbase + S_B + buf * 2 * BBUF;
        uint32_t dl = dh + BBUF;
#pragma unroll
        for (int i = 0; i < CH; i++) {
            int c = tid + i * 256;
            int row = c >> 3, kc = c & 7;
            size_t go = (size_t)(bn + row) * K + k0 + kc * 4;
            uint32_t so = row * 80 + kc * 8;
            cp_async8(dh + so, Bthi + go);
            cp_async8(dl + so, Btlo + go);
        }
        CP_COMMIT();
    };
    auto compute = [&](int buf) {
        uint32_t Ah = sbase + S_A + buf * 2 * ABUF;
        uint32_t Al = Ah + ABUF;
        uint32_t Bh = sbase + S_B + buf * 2 * BBUF;
        uint32_t Bl = Bh + BBUF;
#pragma unroll
        for (int kk = 0; kk < 32; kk += 16) {
            uint32_t ah[2][4], al[2][4];
#pragma unroll
            for (int mi = 0; mi < 2; mi++) {
                uint32_t o = aoff + mi * (16 * 80) + kk * 2;
                ldsm4(ah[mi], Ah + o);
                ldsm4(al[mi], Al + o);
            }
#pragma unroll
            for (int tp = 0; tp < NTILES / 2; tp++) {
                uint32_t o = boff[tp] + kk * 2;
                uint32_t bh4[4], bl4[4];
                ldsm4(bh4, Bh + o);
                ldsm4(bl4, Bl + o);
#pragma unroll
                for (int sub = 0; sub < 2; sub++) {
                    int nt = tp * 2 + sub;
                    const uint32_t* bh = bh4 + sub * 2;
                    const uint32_t* bl = bl4 + sub * 2;
#pragma unroll
                    for (int mi = 0; mi < 2; mi++) {
                        mma16816(acc[mi][nt], ah[mi], bh);
                        mma16816(acc[mi][nt], ah[mi], bl);
                        mma16816(acc[mi][nt], al[mi], bh);
                    }
                }
            }
        }
    };

    int nstages = K / 32;
    float4 ar[4];
    loadA(0, ar);
    loadB(0, 0);
    storeA(ar, 0);
    CP_WAIT0();
    __syncthreads();
    for (int s = 0; s < nstages; s++) {
        int cur = s & 1, nxt = cur ^ 1;
        bool more = (s + 1) < nstages;
        if (more) {
            loadA((s + 1) * 32, ar);
            loadB((s + 1) * 32, nxt);
        }
        compute(cur);
        if (more) storeA(ar, nxt);
        CP_WAIT0();
        __syncthreads();
    }

    // ---- epilogue ----
    const int NT = (BN == 128) ? 256 : 64;
    float sals[2][2], sald[2][2];
    sals[0][0] = sals[0][1] = sals[1][0] = sals[1][1] = 0.f;
    sald[0][0] = sald[0][1] = sald[1][0] = sald[1][1] = 0.f;
#pragma unroll
    for (int mi = 0; mi < 2; mi++) {
        int r0 = bm + warp_m * 32 + mi * 16 + g;
        int r1 = r0 + 8;
#pragma unroll
        for (int nt = 0; nt < NTILES; nt++) {
            int nloc = warp_n * WN + nt * 8 + tg * 2;
            int n0 = bn + nloc;
            float* cc = acc[mi][nt];
            float v00 = cc[0], v01 = cc[1], v10 = cc[2], v11 = cc[3];
            if (BIAS) {
                v00 += sBias[nloc]; v01 += sBias[nloc + 1];
                v10 += sBias[nloc]; v11 += sBias[nloc + 1];
            }
            if (RELU) {
                v00 = fmaxf(v00, 0.f); v01 = fmaxf(v01, 0.f);
                v10 = fmaxf(v10, 0.f); v11 = fmaxf(v11, 0.f);
            }
            if (r0 < M) *(float2*)(cfg.C + (size_t)r0 * NT + n0) = make_float2(v00, v01);
            if (r1 < M) *(float2*)(cfg.C + (size_t)r1 * NT + n0) = make_float2(v10, v11);
            if (HALS) {
                float a0 = sAsrc[nloc], a1 = sAsrc[nloc + 1];
                sals[mi][0] += v00 * a0 + v01 * a1;
                sals[mi][1] += v10 * a0 + v11 * a1;
                if (dual) {
                    float d0 = sAdst[nloc], d1 = sAdst[nloc + 1];
                    sald[mi][0] += v00 * d0 + v01 * d1;
                    sald[mi][1] += v10 * d0 + v11 * d1;
                }
            }
        }
    }
    if (HALS) {
        if (HALS == 1) {
            for (int i = tid; i < 128; i += 256) { sr1[i] = 0.f; sr2[i] = 0.f; }
            __syncthreads();
        }
#pragma unroll
        for (int mi = 0; mi < 2; mi++)
#pragma unroll
            for (int hf = 0; hf < 2; hf++) {
                float s = sals[mi][hf];
                s += __shfl_xor_sync(0xffffffffu, s, 1);
                s += __shfl_xor_sync(0xffffffffu, s, 2);
                float s2 = sald[mi][hf];
                s2 += __shfl_xor_sync(0xffffffffu, s2, 1);
                s2 += __shfl_xor_sync(0xffffffffu, s2, 2);
                if (tg == 0) {
                    int rloc = warp_m * 32 + mi * 16 + g + hf * 8;
                    int r = bm + rloc;
                    if (HALS == 4) {
                        if (r < M) {
                            int h = blockIdx.y * 2 + warp_n;
                            cfg.als[(size_t)r * 4 + h] = s;
                            if (dual) cfg.ald[(size_t)r * 4 + h] = s2;
                        }
                    } else {
                        atomicAdd(&sr1[rloc], s);
                        if (dual) atomicAdd(&sr2[rloc], s2);
                    }
                }
            }
        if (HALS == 1) {
            __syncthreads();
            for (int i = tid; i < 128; i += 256) {
                int r = bm + i;
                if (r < M) {
                    cfg.als[r] = sr1[i];
                    if (dual) cfg.ald[r] = sr2[i];
                }
            }
        }
    }
}

// ---------------- CSR build (batched over 3 edge types) ----------------
__global__ void k_count3(const int* __restrict__ d0, const int* __restrict__ d1,
                         const int* __restrict__ d2, int E0, int E1, int E2,
                         int* __restrict__ cnt) {
    int t = blockIdx.y;
    const int* dst = (t == 0) ? d0 : (t == 1) ? d1 : d2;
    int E = (t == 0) ? E0 : (t == 1) ? E1 : E2;
    int i = blockIdx.x * 256 + threadIdx.x;
    if (i < E) atomicAdd(&cnt[t * NP + dst[i]], 1);
}
// 3 blocks, 1024 threads, 4 elems/thread; also re-zeroes cnt for the scatter pass
__global__ void __launch_bounds__(1024) k_scan3(int* __restrict__ cnt,
                                                int* __restrict__ rp, int n0, int n1, int n2) {
    int t = blockIdx.x;
    int n = (t == 0) ? n0 : (t == 1) ? n1 : n2;
    int* c = cnt + t * NP;
    int* rowptr = rp + t * (NP + 1);
    __shared__ int wsum[32];
    __shared__ int carry_s;
    int tid = threadIdx.x, lane = tid & 31, wid = tid >> 5;
    if (tid == 0) { carry_s = 0; rowptr[0] = 0; }
    __syncthreads();
    for (int base = 0; base < n; base += 4096) {
        int c0 = carry_s;
        int i0 = base + tid * 4;
        int v[4];
#pragma unroll
        for (int k = 0; k < 4; k++) {
            v[k] = (i0 + k < n) ? c[i0 + k] : 0;
            if (i0 + k < n) c[i0 + k] = 0;
        }
        int incl[4];
        incl[0] = v[0];
        incl[1] = incl[0] + v[1];
        incl[2] = incl[1] + v[2];
        incl[3] = incl[2] + v[3];
        int tot = incl[3];
        int x = tot;
#pragma unroll
        for (int o = 1; o < 32; o <<= 1) {
            int y = __shfl_up_sync(0xffffffffu, x, o);
            if (lane >= o) x += y;
        }
        if (lane == 31) wsum[wid] = x;
        __syncthreads();
        if (wid == 0) {
            int s = wsum[lane];
#pragma unroll
            for (int o = 1; o < 32; o <<= 1) {
                int y = __shfl_up_sync(0xffffffffu, s, o);
                if (lane >= o) s += y;
            }
            wsum[lane] = s;
        }
        __syncthreads();
        int excl = (x - tot) + (wid ? wsum[wid - 1] : 0) + c0;
#pragma unroll
        for (int k = 0; k < 4; k++) {
            int i = i0 + k;
            if (i < n) rowptr[i + 1] = excl + incl[k];
        }
        __syncthreads();
        if (tid == 0) carry_s = c0 + wsum[31];
        __syncthreads();
    }
}
// scatter; the thread claiming the LAST slot per dst resets cnt to 0 (so no k_zero
// launch is needed: static init is zero and every replay leaves cnt zeroed)
__global__ void k_scatter3(const int* __restrict__ s0p, const int* __restrict__ s1p,
                           const int* __restrict__ s2p, const int* __restrict__ d0,
                           const int* __restrict__ d1, const int* __restrict__ d2,
                           int E0, int E1, int E2, const int* __restrict__ rp,
                           int* __restrict__ off, int* __restrict__ srcp) {
    int t = blockIdx.y;
    const int* src = (t == 0) ? s0p : (t == 1) ? s1p : s2p;
    const int* dst = (t == 0) ? d0 : (t == 1) ? d1 : d2;
    int E = (t == 0) ? E0 : (t == 1) ? E1 : E2;
    int i = blockIdx.x * 256 + threadIdx.x;
    if (i < E) {
        int d = dst[i];
        int p = rp[t * (NP + 1) + d] + atomicAdd(&off[t * NP + d], 1);
        srcp[t * EMAX + p] = src[i];
        if (p + 1 == rp[t * (NP + 1) + d + 1]) off[t * NP + d] = 0;  // last slot -> clean
    }
}

// ---------------- all 9 Vd vectors in one launch ----------------
__global__ void k_makeV_all(const float* __restrict__ W_hid, const float* __restrict__ ad_hid,
                            const float* __restrict__ W_out, const float* __restrict__ ad_out,
                            float* __restrict__ V) {
    int b = blockIdx.x;
    int k = threadIdx.x;
    if (b < 6) {
        const float* W = W_hid + (size_t)b * 65536;
        const float* a = ad_hid + (size_t)b * 256;
        for (int h = 0; h < 4; h++) {
            float s = 0.f;
            for (int c = 0; c < 64; c++) s = fmaf(W[k * 256 + h * 64 + c], a[h * 64 + c], s);
            V[b * 1024 + k * 4 + h] = s;
        }
    } else {
        const float* W = W_out + (size_t)(b - 6) * 16384;
        const float* a = ad_out + (size_t)(b - 6) * 64;
        float s = 0.f;
        for (int c = 0; c < 64; c++) s = fmaf(W[k * 64 + c], a[c], s);
        V[b * 1024 + k] = s;
    }
}

// ---------------- per-segment softmax+gather accumulate, H=4 ----------------
__device__ __forceinline__ void edge4(const int* __restrict__ rowptr,
                                      const int* __restrict__ srcp,
                                      const float* __restrict__ als, const float* ad,
                                      const float* __restrict__ hsrc,
                                      float* __restrict__ alpha, int w, int lane, int c0,
                                      int c1, int hsel, float4& a0, float4& a1) {
    int s0 = rowptr[w], s1 = rowptr[w + 1];
    int deg = s1 - s0;
    if (deg <= 0) return;
    const float NINF = __int_as_float(0xff800000u);
    if (deg <= 32) {
        int sreg = (lane < deg) ? srcp[s0 + lane] : 0;
        float ex[4];
#pragma unroll
        for (int h = 0; h < 4; h++) {
            float e = NINF;
            if (lane < deg) {
                e = als[(size_t)sreg * 4 + h] + ad[h];
                e = e > 0.f ? e : NEG * e;
            }
            ex[h] = e;
        }
        float inv[4];
#pragma unroll
        for (int h = 0; h < 4; h++) {
            float m = ex[h];
#pragma unroll
            for (int o = 16; o; o >>= 1) m = fmaxf(m, __shfl_xor_sync(0xffffffffu, m, o));
            float v = (lane < deg) ? __expf(ex[h] - m) : 0.f;
            ex[h] = v;
#pragma unroll
            for (int o = 16; o; o >>= 1) v += __shfl_xor_sync(0xffffffffu, v, o);
            inv[h] = 1.f / (v + 1e-16f);
        }
        float inv0 = hsel ? inv[1] : inv[0];
        float inv1 = hsel ? inv[3] : inv[2];
        for (int i = 0; i < deg; i++) {
            int s = __shfl_sync(0xffffffffu, sreg, i);
            float e0 = __shfl_sync(0xffffffffu, ex[0], i);
            float e1 = __shfl_sync(0xffffffffu, ex[1], i);
            float e2 = __shfl_sync(0xffffffffu, ex[2], i);
            float e3 = __shfl_sync(0xffffffffu, ex[3], i);
            float w0 = (hsel ? e1 : e0) * inv0;
            float w1 = (hsel ? e3 : e2) * inv1;
            const float4* hr = (const float4*)(hsrc + (size_t)s * 256);
            float4 v0 = hr[c0], v1 = hr[c1];
            a0.x = fmaf(v0.x, w0, a0.x); a0.y = fmaf(v0.y, w0, a0.y);
            a0.z = fmaf(v0.z, w0, a0.z); a0.w = fmaf(v0.w, w0, a0.w);
            a1.x = fmaf(v1.x, w1, a1.x); a1.y = fmaf(v1.y, w1, a1.y);
            a1.z = fmaf(v1.z, w1, a1.z); a1.w = fmaf(v1.w, w1, a1.w);
        }
    } else {
        float mx[4], sm[4], inv[4];
#pragma unroll
        for (int h = 0; h < 4; h++) { mx[h] = NINF; sm[h] = 0.f; }
        for (int j = s0 + lane; j < s1; j += 32) {
            int s = srcp[j];
#pragma unroll
            for (int h = 0; h < 4; h++) {
                float e = als[(size_t)s * 4 + h] + ad[h];
                e = e > 0.f ? e : NEG * e;
                alpha[(size_t)j * 4 + h] = e;
                mx[h] = fmaxf(mx[h], e);
            }
        }
#pragma unroll
        for (int h = 0; h < 4; h++)
#pragma unroll
            for (int o = 16; o; o >>= 1)
                mx[h] = fmaxf(mx[h], __shfl_xor_sync(0xffffffffu, mx[h], o));
        for (int j = s0 + lane; j < s1; j += 32) {
#pragma unroll
            for (int h = 0; h < 4; h++) {
                float e2 = __expf(alpha[(size_t)j * 4 + h] - mx[h]);
                alpha[(size_t)j * 4 + h] = e2;
                sm[h] += e2;
            }
        }
#pragma unroll
        for (int h = 0; h < 4; h++) {
#pragma unroll
            for (int o = 16; o; o >>= 1) sm[h] += __shfl_xor_sync(0xffffffffu, sm[h], o);
            inv[h] = 1.f / (sm[h] + 1e-16f);
        }
        float inv0 = inv[hsel], inv1 = inv[hsel + 2];
        for (int j = s0; j < s1; j++) {
            int s = srcp[j];
            float4 al = *(const float4*)(alpha + (size_t)j * 4);
            const float4* hr = (const float4*)(hsrc + (size_t)s * 256);
            float4 v0 = hr[c0], v1 = hr[c1];
            float w0 = (hsel ? al.y : al.x) * inv0;
            float w1 = (hsel ? al.w : al.z) * inv1;
            a0.x = fmaf(v0.x, w0, a0.x); a0.y = fmaf(v0.y, w0, a0.y);
            a0.z = fmaf(v0.z, w0, a0.z); a0.w = fmaf(v0.w, w0, a0.w);
            a1.x = fmaf(v1.x, w1, a1.x); a1.y = fmaf(v1.y, w1, a1.y);
            a1.z = fmaf(v1.z, w1, a1.z); a1.w = fmaf(v1.w, w1, a1.w);
        }
    }
}

// ---------------- mega aggregation: one launch per hidden layer ----------------
__global__ void __launch_bounds__(256) k_lagg4(
    const int* __restrict__ rp0, const int* __restrict__ sp0, const int* __restrict__ rp1,
    const int* __restrict__ sp1, const int* __restrict__ rp2, const int* __restrict__ sp2,
    const float* __restrict__ h0, const float* __restrict__ h1, const float* __restrict__ h2,
    const float* __restrict__ als0, const float* __restrict__ als1,
    const float* __restrict__ als2, const float* __restrict__ ald2,
    const float* __restrict__ V0, const float* __restrict__ V1,
    const float* __restrict__ xp_in, const float* __restrict__ xd_in,
    const float* __restrict__ b0, const float* __restrict__ b1, const float* __restrict__ b2,
    float* __restrict__ alpha0, float* __restrict__ alpha1, float* __restrict__ alpha2,
    float* __restrict__ xp_out, float* __restrict__ xd_out, int act) {
    __shared__ float Vs0[1024];
    __shared__ float Vs1[1024];
    for (int i = threadIdx.x; i < 1024; i += 256) {
        Vs0[i] = V0[i];
        Vs1[i] = V1[i];
    }
    __syncthreads();
    int n = (blockIdx.x * 256 + threadIdx.x) >> 5;
    int lane = threadIdx.x & 31;
    if (n >= NP + ND) return;
    int c0 = lane, c1 = lane + 32, hsel = lane >> 4;
    float4 a0 = make_float4(0.f, 0.f, 0.f, 0.f), a1 = a0;
    float4 o0, o1;
    float4* orow;
    if (n < NP) {
        int w = n;
        const float* xr = xp_in + (size_t)w * 256;
        float p[4] = {0.f, 0.f, 0.f, 0.f};
#pragma unroll
        for (int tt = 0; tt < 8; tt++) {
            int k = lane + tt * 32;
            float x = xr[k];
#pragma unroll
            for (int h = 0; h < 4; h++) p[h] = fmaf(x, Vs0[k * 4 + h], p[h]);
        }
        float ad0[4];
#pragma unroll
        for (int h = 0; h < 4; h++) {
#pragma unroll
            for (int o = 16; o; o >>= 1) p[h] += __shfl_xor_sync(0xffffffffu, p[h], o);
            ad0[h] = p[h];
        }
        float ad2[4];
#pragma unroll
        for (int h = 0; h < 4; h++) ad2[h] = ald2[(size_t)w * 4 + h];
        edge4(rp0, sp0, als0, ad0, h0, alpha0, w, lane, c0, c1, hsel, a0, a1);
        edge4(rp2, sp2, als2, ad2, h2, alpha2, w, lane, c0, c1, hsel, a0, a1);
        const float4* B0 = (const float4*)b0;
        const float4* B2 = (const float4*)b2;
        float4 bb0 = B0[c0], bb1 = B0[c1];
        float4 t0 = B2[c0], t1 = B2[c1];
        bb0.x += t0.x; bb0.y += t0.y; bb0.z += t0.z; bb0.w += t0.w;
        bb1.x += t1.x; bb1.y += t1.y; bb1.z += t1.z; bb1.w += t1.w;
        o0 = make_float4(a0.x + bb0.x, a0.y + bb0.y, a0.z + bb0.z, a0.w + bb0.w);
        o1 = make_float4(a1.x + bb1.x, a1.y + bb1.y, a1.z + bb1.z, a1.w + bb1.w);
        orow = (float4*)(xp_out + (size_t)w * 256);
    } else {
        int w = n - NP;
        const float* xr = xd_in + (size_t)w * 256;
        float p[4] = {0.f, 0.f, 0.f, 0.f};
#pragma unroll
        for (int tt = 0; tt < 8; tt++) {
            int k = lane + tt * 32;
            float x = xr[k];
#pragma unroll
            for (int h = 0; h < 4; h++) p[h] = fmaf(x, Vs1[k * 4 + h], p[h]);
        }
        float ad1[4];
#pragma unroll
        for (int h = 0; h < 4; h++) {
#pragma unroll
            for (int o = 16; o; o >>= 1) p[h] += __shfl_xor_sync(0xffffffffu, p[h], o);
            ad1[h] = p[h];
        }
        edge4(rp1, sp1, als1, ad1, h1, alpha1, w, lane, c0, c1, hsel, a0, a1);
        const float4* B1 = (const float4*)b1;
        float4 bb0 = B1[c0], bb1 = B1[c1];
        o0 = make_float4(a0.x + bb0.x, a0.y + bb0.y, a0.z + bb0.z, a0.w + bb0.w);
        o1 = make_float4(a1.x + bb1.x, a1.y + bb1.y, a1.z + bb1.z, a1.w + bb1.w);
        orow = (float4*)(xd_out + (size_t)w * 256);
    }
    if (act) {
        o0.x = eluf(o0.x); o0.y = eluf(o0.y); o0.z = eluf(o0.z); o0.w = eluf(o0.w);
        o1.x = eluf(o1.x); o1.y = eluf(o1.y); o1.z = eluf(o1.z); o1.w = eluf(o1.w);
    }
    orow[c0] = o0;
    orow[c1] = o1;
}

// ---------------- per-segment softmax+gather, H=1, 64 cols ----------------
__device__ __forceinline__ void edge1(const int* __restrict__ rowptr,
                                      const int* __restrict__ srcp,
                                      const float* __restrict__ als, float ad,
                                      const float* __restrict__ hsrc,
                                      float* __restrict__ alpha, int w, int lane, float& a0,
                                      float& a1) {
    int s0 = rowptr[w], s1 = rowptr[w + 1];
    int deg = s1 - s0;
    if (deg <= 0) return;
    const float NINF = __int_as_float(0xff800000u);
    if (deg <= 32) {
        int sreg = (lane < deg) ? srcp[s0 + lane] : 0;
        float e = NINF;
        if (lane < deg) {
            e = als[sreg] + ad;
            e = e > 0.f ? e : NEG * e;
        }
        float m = e;
#pragma unroll
        for (int o = 16; o; o >>= 1) m = fmaxf(m, __shfl_xor_sync(0xffffffffu, m, o));
        float ex = (lane < deg) ? __expf(e - m) : 0.f;
        float sm = ex;
#pragma unroll
        for (int o = 16; o; o >>= 1) sm += __shfl_xor_sync(0xffffffffu, sm, o);
        float inv = 1.f / (sm + 1e-16f);
        for (int i = 0; i < deg; i++) {
            int s = __shfl_sync(0xffffffffu, sreg, i);
            float al = __shfl_sync(0xffffffffu, ex, i) * inv;
            const float* hr = hsrc + (size_t)s * 64;
            a0 = fmaf(hr[lane], al, a0);
            a1 = fmaf(hr[lane + 32], al, a1);
        }
    } else {
        float mx = NINF, sm = 0.f;
        for (int j = s0 + lane; j < s1; j += 32) {
            int s = srcp[j];
            float e = als[s] + ad;
            e = e > 0.f ? e : NEG * e;
            alpha[j] = e;
            mx = fmaxf(mx, e);
        }
#pragma unroll
        for (int o = 16; o; o >>= 1) mx = fmaxf(mx, __shfl_xor_sync(0xffffffffu, mx, o));
        for (int j = s0 + lane; j < s1; j += 32) {
            float ex = __expf(alpha[j] - mx);
            alpha[j] = ex;
            sm += ex;
        }
#pragma unroll
        for (int o = 16; o; o >>= 1) sm += __shfl_xor_sync(0xffffffffu, sm, o);
        float inv = 1.f / (sm + 1e-16f);
        for (int j = s0; j < s1; j++) {
            int s = srcp[j];
            float al = alpha[j] * inv;
            const float* hr = hsrc + (size_t)s * 64;
            a0 = fmaf(hr[lane], al, a0);
            a1 = fmaf(hr[lane + 32], al, a1);
        }
    }
}

// ---------------- mega aggregation for output layer ----------------
__global__ void __launch_bounds__(256) k_lagg1(
    const int* __restrict__ rp0, const int* __restrict__ sp0, const int* __restrict__ rp1,
    const int* __restrict__ sp1, const int* __restrict__ rp2, const int* __restrict__ sp2,
    const float* __restrict__ h0, const float* __restrict__ h1, const float* __restrict__ h2,
    const float* __restrict__ als0, const float* __restrict__ als1,
    const float* __restrict__ als2, const float* __restrict__ ald2,
    const float* __restrict__ V0, const float* __restrict__ V1,
    const float* __restrict__ xp_in, const float* __restrict__ xd_in,
    const float* __restrict__ b0, const float* __restrict__ b1, const float* __restrict__ b2,
    float* __restrict__ alpha0, float* __restrict__ alpha1, float* __restrict__ alpha2,
    float* __restrict__ op, float* __restrict__ od) {
    __shared__ float Vs0[256];
    __shared__ float Vs1[256];
    for (int i = threadIdx.x; i < 256; i += 256) {
        Vs0[i] = V0[i];
        Vs1[i] = V1[i];
    }
    __syncthreads();
    int n = (blockIdx.x * 256 + threadIdx.x) >> 5;
    int lane = threadIdx.x & 31;
    if (n >= NP + ND) return;
    float a0 = 0.f, a1 = 0.f;
    float* orow;
    float bb0, bb1;
    if (n < NP) {
        int w = n;
        const float* xr = xp_in + (size_t)w * 256;
        float p = 0.f;
#pragma unroll
        for (int tt = 0; tt < 8; tt++) {
            int k = lane + tt * 32;
            p = fmaf(xr[k], Vs0[k], p);
        }
#pragma unroll
        for (int o = 16; o; o >>= 1) p += __shfl_xor_sync(0xffffffffu, p, o);
        edge1(rp0, sp0, als0, p, h0, alpha0, w, lane, a0, a1);
        edge1(rp2, sp2, als2, ald2[w], h2, alpha2, w, lane, a0, a1);
        bb0 = b0[lane] + b2[lane];
        bb1 = b0[lane + 32] + b2[lane + 32];
        orow = op + (size_t)w * 64;
    } else {
        int w = n - NP;
        const float* xr = xd_in + (size_t)w * 256;
        float p = 0.f;
#pragma unroll
        for (int tt = 0; tt < 8; tt++) {
            int k = lane + tt * 32;
            p = fmaf(xr[k], Vs1[k], p);
        }
#pragma unroll
        for (int o = 16; o; o >>= 1) p += __shfl_xor_sync(0xffffffffu, p, o);
        edge1(rp1, sp1, als1, p, h1, alpha1, w, lane, a0, a1);
        bb0 = b1[lane];
        bb1 = b1[lane + 32];
        orow = od + (size_t)w * 64;
    }
    orow[lane] = a0 + bb0;
    orow[lane + 32] = a1 + bb1;
}

// =====================================================================
extern "C" void kernel_launch(void* const* d_in, const int* in_sizes, int n_in,
                              void* d_out, int out_size) {
    const float* x_drug = (const float*)d_in[0];
    const float* x_prot = (const float*)d_in[1];
    const int* srcA[3] = {(const int*)d_in[2], (const int*)d_in[4], (const int*)d_in[6]};
    const int* dstA[3] = {(const int*)d_in[3], (const int*)d_in[5], (const int*)d_in[7]};
    const float* linW_d = (const float*)d_in[8];
    const float* linb_d = (const float*)d_in[9];
    const float* linW_p = (const float*)d_in[10];
    const float* linb_p = (const float*)d_in[11];
    const float* W_hid = (const float*)d_in[12];
    const float* as_hid = (const float*)d_in[13];
    const float* ad_hid = (const float*)d_in[14];
    const float* b_hid = (const float*)d_in[15];
    const float* W_out = (const float*)d_in[16];
    const float* as_out = (const float*)d_in[17];
    const float* ad_out = (const float*)d_in[18];
    const float* b_out = (const float*)d_in[19];
    float* outp = (float*)d_out;

    int E[3] = {in_sizes[2], in_sizes[4], in_sizes[6]};
    int maxE = E[0] > E[1] ? E[0] : E[1];
    if (E[2] > maxE) maxE = E[2];

    float *xdb, *xpb, *hb, *alpha, *als, *ald, *V;
    int *rp, *sp, *cnt;
    __nv_bfloat16 *whi, *wlo;
    cudaGetSymbolAddress((void**)&xdb, g_xd);
    cudaGetSymbolAddress((void**)&xpb, g_xp);
    cudaGetSymbolAddress((void**)&hb, g_h);
    cudaGetSymbolAddress((void**)&alpha, g_alpha);
    cudaGetSymbolAddress((void**)&als, g_als);
    cudaGetSymbolAddress((void**)&ald, g_ald);
    cudaGetSymbolAddress((void**)&V, g_V);
    cudaGetSymbolAddress((void**)&rp, g_rowptr);
    cudaGetSymbolAddress((void**)&sp, g_srcp);
    cudaGetSymbolAddress((void**)&cnt, g_cnt);
    cudaGetSymbolAddress((void**)&whi, g_whi);
    cudaGetSymbolAddress((void**)&wlo, g_wlo);

    float* xd[2] = {xdb, xdb + (size_t)ND * HIDW};
    float* xp[2] = {xpb, xpb + (size_t)NP * HIDW};
    float* h0 = hb;
    float* h1 = hb + (size_t)NP * HIDW;
    float* h2 = hb + 2 * (size_t)NP * HIDW;
    int* rowptr[3] = {rp, rp + (NP + 1), rp + 2 * (NP + 1)};
    int* srcp[3] = {sp, sp + EMAX, sp + 2 * EMAX};
    float* als0 = als;
    float* als1 = als + (size_t)NP * 4;
    float* als2 = als + 2 * (size_t)NP * 4;
    float* alpha0 = alpha;
    float* alpha1 = alpha + (size_t)EMAX * 4;
    float* alpha2 = alpha + 2 * (size_t)EMAX * 4;

    const int SM128 = 2048 + 4 * (128 * 40 * 2) + 4 * (128 * 40 * 2);  // 83968
    const int SM64 = 2048 + 4 * (128 * 40 * 2) + 4 * (64 * 40 * 2);    // 63488
    cudaFuncSetAttribute(k_mma<128, true, true, 0>,
                         cudaFuncAttributeMaxDynamicSharedMemorySize, SM128);
    cudaFuncSetAttribute(k_mma<128, false, false, 4>,
                         cudaFuncAttributeMaxDynamicSharedMemorySize, SM128);
    cudaFuncSetAttribute(k_mma<64, false, false, 1>,
                         cudaFuncAttributeMaxDynamicSharedMemorySize, SM64);

    size_t o_lind = 0;
    size_t o_linp = 32768;
    size_t o_hid0 = 98304;
    size_t o_out0 = 491520;

    int ebx = (maxE + 255) / 256;
    int gx128 = (NP + 127) / 128;

    // L0: count (cnt is zero: static-init on first run, self-cleaned by scatter after)
    {
        dim3 gc(ebx, 3);
        k_count3<<<gc, 256>>>(dstA[0], dstA[1], dstA[2], E[0], E[1], E[2], cnt);
    }
    // L1: weight split
    {
        dim3 gw(256, 11);
        k_splitW_all<<<gw, 256>>>(linW_d, linW_p, W_hid, W_out, whi, wlo);
    }
    // L2: input projections (batched z=2)
    {
        GemmCfg3 P{};
        P.c[0] = {x_drug, whi + o_lind, wlo + o_lind, linb_d, nullptr, nullptr,
                  xd[0], nullptr, nullptr, ND, 128};
        P.c[1] = {x_prot, whi + o_linp, wlo + o_linp, linb_p, nullptr, nullptr,
                  xp[0], nullptr, nullptr, NP, 256};
        P.c[2] = P.c[1];
        dim3 gg(gx128, 2, 2);
        k_mma<128, true, true, 0><<<gg, 256, SM128>>>(P);
    }
    // L3: scan (+re-zero cnt for scatter offsets)
    k_scan3<<<3, 1024>>>(cnt, rp, NP, ND, NP);
    // L4: scatter (self-cleans cnt)
    {
        dim3 gs(ebx, 3);
        k_scatter3<<<gs, 256>>>(srcA[0], srcA[1], srcA[2], dstA[0], dstA[1], dstA[2], E[0],
                                E[1], E[2], rp, cnt, sp);
    }
    // L5: V vectors
    k_makeV_all<<<9, 256>>>(W_hid, ad_hid, W_out, ad_out, V);

    int cur = 0, nxt = 1;
    int naggb = (NP + ND + 7) / 8;

    // ---- hidden layers ----
    for (int l = 0; l < 2; l++) {
        int i0 = l * 3 + 0, i1 = l * 3 + 1, i2 = l * 3 + 2;
        {
            GemmCfg3 P{};
            P.c[0] = {xd[cur], whi + o_hid0 + (size_t)i0 * 65536,
                      wlo + o_hid0 + (size_t)i0 * 65536, nullptr,
                      as_hid + (size_t)i0 * 256, nullptr, h0, als0, nullptr, ND, 256};
            P.c[1] = {xp[cur], whi + o_hid0 + (size_t)i1 * 65536,
                      wlo + o_hid0 + (size_t)i1 * 65536, nullptr,
                      as_hid + (size_t)i1 * 256, nullptr, h1, als1, nullptr, NP, 256};
            P.c[2] = {xp[cur], whi + o_hid0 + (size_t)i2 * 65536,
                      wlo + o_hid0 + (size_t)i2 * 65536, nullptr,
                      as_hid + (size_t)i2 * 256, ad_hid + (size_t)i2 * 256, h2, als2, ald,
                      NP, 256};
            dim3 gg(gx128, 2, 3);
            k_mma<128, false, false, 4><<<gg, 256, SM128>>>(P);
        }
        k_lagg4<<<naggb, 256>>>(rowptr[0], srcp[0], rowptr[1], srcp[1], rowptr[2], srcp[2],
                                h0, h1, h2, als0, als1, als2, ald, V + (size_t)i0 * 1024,
                                V + (size_t)i1 * 1024, xp[cur], xd[cur],
                                b_hid + (size_t)i0 * 256, b_hid + (size_t)i1 * 256,
                                b_hid + (size_t)i2 * 256, alpha0, alpha1, alpha2, xp[nxt],
                                xd[nxt], 1);
        cur = nxt;
        nxt = 1 - nxt;
    }

    // ---- output layer ----
    float* od = outp;
    float* op = outp + (size_t)ND * OUTC;
    {
        GemmCfg3 P{};
        P.c[0] = {xd[cur], whi + o_out0, wlo + o_out0, nullptr, as_out, nullptr,
                  h0, als0, nullptr, ND, 256};
        P.c[1] = {xp[cur], whi + o_out0 + 16384, wlo + o_out0 + 16384, nullptr,
                  as_out + OUTC, nullptr, h1, als1, nullptr, NP, 256};
        P.c[2] = {xp[cur], whi + o_out0 + 2 * 16384, wlo + o_out0 + 2 * 16384, nullptr,
                  as_out + 2 * OUTC, ad_out + 2 * OUTC, h2, als2, ald, NP, 256};
        dim3 gg(gx128, 1, 3);
        k_mma<64, false, false, 1><<<gg, 256, SM64>>>(P);
    }
    k_lagg1<<<naggb, 256>>>(rowptr[0], srcp[0], rowptr[1], srcp[1], rowptr[2], srcp[2], h0,
                            h1, h2, als0, als1, als2, ald, V + 6 * 1024, V + 7 * 1024,
                            xp[cur], xd[cur], b_out + 0 * OUTC, b_out + 1 * OUTC,
                            b_out + 2 * OUTC, alpha0, alpha1, alpha2, op, od);

    (void)n_in;
    (void)out_size;
}